// round 1
// baseline (speedup 1.0000x reference)
#include <cuda_runtime.h>

#define SIGMA 10.0f
#define RHO   28.0f
#define BETA  (8.0f / 3.0f)
#define DT    0.01f
#define TSTEPS 64

__device__ __forceinline__ void lorenz_f(float x, float y, float z,
                                         float& dx, float& dy, float& dz) {
    dx = SIGMA * (y - x);
    dy = x * (RHO - z) - y;
    dz = x * y - BETA * z;
}

__global__ void __launch_bounds__(256)
lya_spec_kernel(const float* __restrict__ x_in,
                const float* __restrict__ tseq,
                float* __restrict__ out,
                int B, int write_xf)
{
    __shared__ float s_t[TSTEPS];
    if (threadIdx.x < TSTEPS) s_t[threadIdx.x] = tseq[threadIdx.x];
    __syncthreads();

    int b = blockIdx.x * blockDim.x + threadIdx.x;
    if (b >= B) return;

    // trajectory state
    float xx = x_in[b];
    float yy = x_in[B + b];
    float zz = x_in[2 * B + b];

    // tangent basis Q (rows), starts as identity
    float Q00 = 1.f, Q01 = 0.f, Q02 = 0.f;
    float Q10 = 0.f, Q11 = 1.f, Q12 = 0.f;
    float Q20 = 0.f, Q21 = 0.f, Q22 = 1.f;

    float ly0 = 0.f, ly1 = 0.f, ly2 = 0.f;

    const float dt = DT;

    #pragma unroll 1
    for (int s = 0; s < TSTEPS; ++s) {
        float t = s_t[s];

        // ---- RK4 (faithful to reference: k4 evaluated at x + dt*k2) ----
        float k1x, k1y, k1z, k2x, k2y, k2z, k3x, k3y, k3z, k4x, k4y, k4z;
        lorenz_f(xx, yy, zz, k1x, k1y, k1z);

        float h = dt * 0.5f;
        lorenz_f(xx + h * k1x, yy + h * k1y, zz + h * k1z, k2x, k2y, k2z);
        lorenz_f(xx + h * k2x, yy + h * k2y, zz + h * k2z, k3x, k3y, k3z);
        lorenz_f(xx + dt * k2x, yy + dt * k2y, zz + dt * k2z, k4x, k4y, k4z);

        const float c6 = 1.0f / 6.0f;
        xx = xx + dt * (k1x + 2.0f * k2x + 2.0f * k3x + k4x) * c6;
        yy = yy + dt * (k1y + 2.0f * k2y + 2.0f * k3y + k4y) * c6;
        zz = zz + dt * (k1z + 2.0f * k2z + 2.0f * k3z + k4z) * c6;

        // ---- tangent propagator P = I + dt*J(x_new) ----
        float P00 = 1.f - dt * SIGMA, P01 = dt * SIGMA,     P02 = 0.f;
        float P10 = dt * (RHO - zz),  P11 = 1.f - dt,       P12 = -dt * xx;
        float P20 = dt * yy,          P21 = dt * xx,        P22 = 1.f - dt * BETA;

        // ---- Q = P @ Q ----
        float N00 = P00 * Q00 + P01 * Q10 + P02 * Q20;
        float N01 = P00 * Q01 + P01 * Q11 + P02 * Q21;
        float N02 = P00 * Q02 + P01 * Q12 + P02 * Q22;
        float N10 = P10 * Q00 + P11 * Q10 + P12 * Q20;
        float N11 = P10 * Q01 + P11 * Q11 + P12 * Q21;
        float N12 = P10 * Q02 + P11 * Q12 + P12 * Q22;
        float N20 = P20 * Q00 + P21 * Q10 + P22 * Q20;
        float N21 = P20 * Q01 + P21 * Q11 + P22 * Q21;
        float N22 = P20 * Q02 + P21 * Q12 + P22 * Q22;

        // ---- modified Gram-Schmidt over rows ----
        // row1 -= (r0.r1 / r0.r0) * row0
        float d00 = N00 * N00 + N01 * N01 + N02 * N02;
        float d01 = N00 * N10 + N01 * N11 + N02 * N12;
        float c10 = __fdividef(d01, d00);
        N10 -= c10 * N00;
        N11 -= c10 * N01;
        N12 -= c10 * N02;

        // row2 -= (r0.r2 / r0.r0) * row0
        float d02 = N00 * N20 + N01 * N21 + N02 * N22;
        float c20 = __fdividef(d02, d00);
        N20 -= c20 * N00;
        N21 -= c20 * N01;
        N22 -= c20 * N02;

        // row2 -= (r1.r2 / r1.r1) * row1
        float d11 = N10 * N10 + N11 * N11 + N12 * N12;
        float d12 = N10 * N20 + N11 * N21 + N12 * N22;
        float c21 = __fdividef(d12, d11);
        N20 -= c21 * N10;
        N21 -= c21 * N11;
        N22 -= c21 * N12;

        // ---- normalize rows, accumulate Lyapunov sums ----
        float n0sq = N00 * N00 + N01 * N01 + N02 * N02;
        float n1sq = N10 * N10 + N11 * N11 + N12 * N12;
        float n2sq = N20 * N20 + N21 * N21 + N22 * N22;

        float r0 = rsqrtf(n0sq);
        float r1 = rsqrtf(n1sq);
        float r2 = rsqrtf(n2sq);

        Q00 = N00 * r0; Q01 = N01 * r0; Q02 = N02 * r0;
        Q10 = N10 * r1; Q11 = N11 * r1; Q12 = N12 * r1;
        Q20 = N20 * r2; Q21 = N21 * r2; Q22 = N22 * r2;

        // log(norm) = 0.5 * log(norm^2)
        float l0 = 0.5f * __logf(n0sq);
        float l1 = 0.5f * __logf(n1sq);
        float l2 = 0.5f * __logf(n2sq);

        float inv = __fdividef(1.0f, t + dt);
        ly0 = (ly0 * t + l0) * inv;
        ly1 = (ly1 * t + l1) * inv;
        ly2 = (ly2 * t + l2) * inv;
    }

    // output: lya [3,B] then xf [3,B]
    out[b]         = ly0;
    out[B + b]     = ly1;
    out[2 * B + b] = ly2;
    if (write_xf) {
        out[3 * B + b] = xx;
        out[4 * B + b] = yy;
        out[5 * B + b] = zz;
    }
}

extern "C" void kernel_launch(void* const* d_in, const int* in_sizes, int n_in,
                              void* d_out, int out_size) {
    const float* x    = (const float*)d_in[0];
    const float* tseq = (const float*)d_in[1];
    float* out = (float*)d_out;

    int B = in_sizes[0] / 3;          // x is [3, B]
    int write_xf = (out_size >= 6 * B) ? 1 : 0;

    int threads = 256;
    int blocks = (B + threads - 1) / threads;
    lya_spec_kernel<<<blocks, threads>>>(x, tseq, out, B, write_xf);
}

// round 2
// speedup vs baseline: 1.1230x; 1.1230x over previous
#include <cuda_runtime.h>
#include <cstdint>

#define SIGMA 10.0f
#define RHO   28.0f
#define BETA  (8.0f / 3.0f)
#define DT    0.01f
#define TSTEPS 64

using u64 = unsigned long long;

// ---- packed f32x2 primitives (Blackwell FFMA2 path) ----
__device__ __forceinline__ u64 f2fma(u64 a, u64 b, u64 c) {
    u64 d; asm("fma.rn.f32x2 %0, %1, %2, %3;" : "=l"(d) : "l"(a), "l"(b), "l"(c)); return d;
}
__device__ __forceinline__ u64 f2add(u64 a, u64 b) {
    u64 d; asm("add.rn.f32x2 %0, %1, %2;" : "=l"(d) : "l"(a), "l"(b)); return d;
}
__device__ __forceinline__ u64 f2mul(u64 a, u64 b) {
    u64 d; asm("mul.rn.f32x2 %0, %1, %2;" : "=l"(d) : "l"(a), "l"(b)); return d;
}
__device__ __forceinline__ u64 f2neg(u64 a) { return a ^ 0x8000000080000000ULL; }

__device__ __forceinline__ u64 pk2(float f) {
    unsigned u = __float_as_uint(f);
    return (u64)u * 0x0000000100000001ULL;
}
// a - b  (one fma-pipe instr, no extra ALU)
__device__ __forceinline__ u64 f2sub(u64 a, u64 b, u64 NEG1) { return f2fma(b, NEG1, a); }

__device__ __forceinline__ u64 f2rsqrt(u64 a) {
    float lo = __uint_as_float((unsigned)a);
    float hi = __uint_as_float((unsigned)(a >> 32));
    lo = rsqrtf(lo);
    hi = rsqrtf(hi);
    return (u64)__float_as_uint(lo) | ((u64)__float_as_uint(hi) << 32);
}

__device__ __forceinline__ u64 dot3(u64 a0, u64 a1, u64 a2, u64 b0, u64 b1, u64 b2) {
    return f2fma(a2, b2, f2fma(a1, b1, f2mul(a0, b0)));
}

__global__ void __launch_bounds__(128, 7)
lya_spec_kernel(const float* __restrict__ x_in,
                const float* __restrict__ tseq,
                float* __restrict__ out,
                int B, int T, int write_xf)
{
    int i = blockIdx.x * blockDim.x + threadIdx.x;   // pair index
    int B2 = B >> 1;
    if (i >= B2) return;

    const u64 NEG1   = pk2(-1.0f);
    const u64 C_SIG  = pk2(SIGMA);
    const u64 C_RHO  = pk2(RHO);
    const u64 C_NBETA= pk2(-BETA);
    const u64 C_HDT  = pk2(0.5f * DT);
    const u64 C_DT   = pk2(DT);
    const u64 C_TWO  = pk2(2.0f);
    const u64 C_DT6  = pk2(DT / 6.0f);
    const u64 C_SDT  = pk2(SIGMA * DT);
    const u64 C_NDT  = pk2(-DT);
    const u64 C_RHODT= pk2(RHO * DT);
    const u64 C_1MDT = pk2(1.0f - DT);
    const u64 C_1MBDT= pk2(1.0f - BETA * DT);
    const u64 ONE    = pk2(1.0f);
    const u64 ZERO   = 0ULL;

    // load 2 adjacent trajectories as packed pairs (coalesced 64-bit loads)
    const u64* xr = (const u64*)x_in;
    int rb = B2;                       // row stride in pairs
    u64 X = xr[i];
    u64 Y = xr[rb + i];
    u64 Z = xr[2 * rb + i];

    u64 Q00 = ONE,  Q01 = ZERO, Q02 = ZERO;
    u64 Q10 = ZERO, Q11 = ONE,  Q12 = ZERO;
    u64 Q20 = ZERO, Q21 = ZERO, Q22 = ONE;

    u64 P0 = ONE, P1 = ONE, P2 = ONE;   // running products of row norm^2

    #pragma unroll 1
    for (int s = 0; s < TSTEPS; ++s) {
        // ---------- RK4 (faithful: k4 at x + dt*k2) ----------
        // k1
        u64 k1x = f2mul(C_SIG, f2sub(Y, X, NEG1));
        u64 k1y = f2fma(X, f2fma(Z, NEG1, C_RHO), f2neg(Y));
        u64 k1z = f2fma(X, Y, f2mul(C_NBETA, Z));
        // k2 at x + h*k1
        u64 ax = f2fma(C_HDT, k1x, X);
        u64 ay = f2fma(C_HDT, k1y, Y);
        u64 az = f2fma(C_HDT, k1z, Z);
        u64 k2x = f2mul(C_SIG, f2sub(ay, ax, NEG1));
        u64 k2y = f2fma(ax, f2fma(az, NEG1, C_RHO), f2neg(ay));
        u64 k2z = f2fma(ax, ay, f2mul(C_NBETA, az));
        // k3 at x + h*k2
        ax = f2fma(C_HDT, k2x, X);
        ay = f2fma(C_HDT, k2y, Y);
        az = f2fma(C_HDT, k2z, Z);
        u64 k3x = f2mul(C_SIG, f2sub(ay, ax, NEG1));
        u64 k3y = f2fma(ax, f2fma(az, NEG1, C_RHO), f2neg(ay));
        u64 k3z = f2fma(ax, ay, f2mul(C_NBETA, az));
        // k4 at x + dt*k2 (reference bug kept)
        ax = f2fma(C_DT, k2x, X);
        ay = f2fma(C_DT, k2y, Y);
        az = f2fma(C_DT, k2z, Z);
        u64 k4x = f2mul(C_SIG, f2sub(ay, ax, NEG1));
        u64 k4y = f2fma(ax, f2fma(az, NEG1, C_RHO), f2neg(ay));
        u64 k4z = f2fma(ax, ay, f2mul(C_NBETA, az));

        X = f2fma(C_DT6, f2fma(C_TWO, f2add(k2x, k3x), f2add(k1x, k4x)), X);
        Y = f2fma(C_DT6, f2fma(C_TWO, f2add(k2y, k3y), f2add(k1y, k4y)), Y);
        Z = f2fma(C_DT6, f2fma(C_TWO, f2add(k2z, k3z), f2add(k1z, k4z)), Z);

        // ---------- N = (I + dt*J(x)) @ Q ----------
        u64 w10  = f2fma(Z, C_NDT, C_RHODT);    // dt*(RHO - z)
        u64 xdt  = f2mul(X, C_DT);
        u64 nxdt = f2neg(xdt);
        u64 ydt  = f2mul(Y, C_DT);

        // row0: Q0 + sigma*dt*(Q1 - Q0)
        u64 N00 = f2fma(C_SDT, f2sub(Q10, Q00, NEG1), Q00);
        u64 N01 = f2fma(C_SDT, f2sub(Q11, Q01, NEG1), Q01);
        u64 N02 = f2fma(C_SDT, f2sub(Q12, Q02, NEG1), Q02);
        // row1: w10*Q0 + (1-dt)*Q1 - x*dt*Q2
        u64 N10 = f2fma(w10, Q00, f2fma(nxdt, Q20, f2mul(C_1MDT, Q10)));
        u64 N11 = f2fma(w10, Q01, f2fma(nxdt, Q21, f2mul(C_1MDT, Q11)));
        u64 N12 = f2fma(w10, Q02, f2fma(nxdt, Q22, f2mul(C_1MDT, Q12)));
        // row2: y*dt*Q0 + x*dt*Q1 + (1-beta*dt)*Q2
        u64 N20 = f2fma(ydt, Q00, f2fma(xdt, Q10, f2mul(C_1MBDT, Q20)));
        u64 N21 = f2fma(ydt, Q01, f2fma(xdt, Q11, f2mul(C_1MBDT, Q21)));
        u64 N22 = f2fma(ydt, Q02, f2fma(xdt, Q12, f2mul(C_1MBDT, Q22)));

        // ---------- MGS (1/d via rsqrt^2, reuses normalization rsqrt) ----------
        u64 d00 = dot3(N00, N01, N02, N00, N01, N02);
        u64 r0 = f2rsqrt(d00);
        u64 nrr0 = f2neg(f2mul(r0, r0));               // -1/d00

        u64 d01 = dot3(N00, N01, N02, N10, N11, N12);
        u64 c10n = f2mul(d01, nrr0);
        N10 = f2fma(c10n, N00, N10);
        N11 = f2fma(c10n, N01, N11);
        N12 = f2fma(c10n, N02, N12);

        u64 d02 = dot3(N00, N01, N02, N20, N21, N22);
        u64 c20n = f2mul(d02, nrr0);
        N20 = f2fma(c20n, N00, N20);
        N21 = f2fma(c20n, N01, N21);
        N22 = f2fma(c20n, N02, N22);

        u64 d11 = dot3(N10, N11, N12, N10, N11, N12);
        u64 r1 = f2rsqrt(d11);
        u64 nrr1 = f2neg(f2mul(r1, r1));               // -1/d11

        u64 d12 = dot3(N10, N11, N12, N20, N21, N22);
        u64 c21n = f2mul(d12, nrr1);
        N20 = f2fma(c21n, N10, N20);
        N21 = f2fma(c21n, N11, N21);
        N22 = f2fma(c21n, N12, N22);

        u64 d22 = dot3(N20, N21, N22, N20, N21, N22);
        u64 r2 = f2rsqrt(d22);

        // normalize rows
        Q00 = f2mul(N00, r0); Q01 = f2mul(N01, r0); Q02 = f2mul(N02, r0);
        Q10 = f2mul(N10, r1); Q11 = f2mul(N11, r1); Q12 = f2mul(N12, r1);
        Q20 = f2mul(N20, r2); Q21 = f2mul(N21, r2); Q22 = f2mul(N22, r2);

        // accumulate products of norm^2 (logs deferred to the end)
        P0 = f2mul(P0, d00);
        P1 = f2mul(P1, d11);
        P2 = f2mul(P2, d22);
    }

    // lya = (sum of log norms) / (t_last + dt) = 0.5*log(prod n^2) / (t_last + dt)
    float tl = tseq[T - 1];
    float sc = __fdividef(0.5f, tl + DT);

    float2* o2 = (float2*)out;
    {
        float lo = sc * __logf(__uint_as_float((unsigned)P0));
        float hi = sc * __logf(__uint_as_float((unsigned)(P0 >> 32)));
        o2[i] = make_float2(lo, hi);
        lo = sc * __logf(__uint_as_float((unsigned)P1));
        hi = sc * __logf(__uint_as_float((unsigned)(P1 >> 32)));
        o2[rb + i] = make_float2(lo, hi);
        lo = sc * __logf(__uint_as_float((unsigned)P2));
        hi = sc * __logf(__uint_as_float((unsigned)(P2 >> 32)));
        o2[2 * rb + i] = make_float2(lo, hi);
    }
    if (write_xf) {
        u64* o8 = (u64*)out;
        o8[3 * rb + i] = X;
        o8[4 * rb + i] = Y;
        o8[5 * rb + i] = Z;
    }
}

extern "C" void kernel_launch(void* const* d_in, const int* in_sizes, int n_in,
                              void* d_out, int out_size) {
    const float* x    = (const float*)d_in[0];
    const float* tseq = (const float*)d_in[1];
    float* out = (float*)d_out;

    int B = in_sizes[0] / 3;          // x is [3, B]
    int T = in_sizes[1];
    int write_xf = (out_size >= 6 * B) ? 1 : 0;

    int B2 = B >> 1;                  // 2 trajectories per thread
    int threads = 128;
    int blocks = (B2 + threads - 1) / threads;
    lya_spec_kernel<<<blocks, threads>>>(x, tseq, out, B, T, write_xf);
}

// round 3
// speedup vs baseline: 1.7994x; 1.6024x over previous
#include <cuda_runtime.h>

#define SIGMA 10.0f
#define RHO   28.0f
#define BETA  (8.0f / 3.0f)
#define DT    0.01f
#define TSTEPS 64

using u64 = unsigned long long;

// ---- packed f32x2 primitives (Blackwell FFMA2 path) ----
__device__ __forceinline__ u64 f2fma(u64 a, u64 b, u64 c) {
    u64 d; asm("fma.rn.f32x2 %0, %1, %2, %3;" : "=l"(d) : "l"(a), "l"(b), "l"(c)); return d;
}
__device__ __forceinline__ u64 f2add(u64 a, u64 b) {
    u64 d; asm("add.rn.f32x2 %0, %1, %2;" : "=l"(d) : "l"(a), "l"(b)); return d;
}
__device__ __forceinline__ u64 f2mul(u64 a, u64 b) {
    u64 d; asm("mul.rn.f32x2 %0, %1, %2;" : "=l"(d) : "l"(a), "l"(b)); return d;
}
__device__ __forceinline__ u64 f2neg(u64 a) { return a ^ 0x8000000080000000ULL; }

__device__ __forceinline__ u64 pk2(float f) {
    unsigned u = __float_as_uint(f);
    return (u64)u * 0x0000000100000001ULL;
}
// a - b via fma(b, -1, a): stays on fma pipe
__device__ __forceinline__ u64 f2sub(u64 a, u64 b, u64 NEG1) { return f2fma(b, NEG1, a); }

// packed reciprocal via 2x MUFU rcp.approx
__device__ __forceinline__ u64 f2rcp(u64 a) {
    float lo = __uint_as_float((unsigned)a);
    float hi = __uint_as_float((unsigned)(a >> 32));
    float rl, rh;
    asm("rcp.approx.f32 %0, %1;" : "=f"(rl) : "f"(lo));
    asm("rcp.approx.f32 %0, %1;" : "=f"(rh) : "f"(hi));
    return (u64)__float_as_uint(rl) | ((u64)__float_as_uint(rh) << 32);
}

__global__ void __launch_bounds__(128, 7)
lya_spec_kernel(const float* __restrict__ x_in,
                const float* __restrict__ tseq,
                float* __restrict__ out,
                int B, int T, int write_xf)
{
    int i = blockIdx.x * blockDim.x + threadIdx.x;   // pair index
    int B2 = B >> 1;
    if (i >= B2) return;

    // ---- compile-time-ish constants ----
    const float a_f   = 1.0f + DT * (-SIGMA);   // 0.9
    const float s_f   = DT * SIGMA;             // 0.1
    const float d00_f = a_f * a_f + s_f * s_f;  // 0.82 (constant row-0 norm^2)
    const float i00_f = 1.0f / d00_f;

    const u64 NEG1    = pk2(-1.0f);
    const u64 C_SIG   = pk2(SIGMA);
    const u64 C_RHO   = pk2(RHO);
    const u64 C_NBETA = pk2(-BETA);
    const u64 C_HDT   = pk2(0.5f * DT);
    const u64 C_DT    = pk2(DT);
    const u64 C_TWO   = pk2(2.0f);
    const u64 C_DT6   = pk2(DT / 6.0f);
    const u64 C_NDT   = pk2(-DT);
    const u64 C_RHODT = pk2(RHO * DT);
    const u64 C_A     = pk2(a_f);
    const u64 C_NA    = pk2(-a_f);
    const u64 C_S     = pk2(s_f);
    const u64 C_NS    = pk2(-s_f);
    const u64 C_99    = pk2(1.0f - DT);           // 0.99
    const u64 C_S99   = pk2(s_f * (1.0f - DT));   // s*(1-dt)
    const u64 C_I00   = pk2(i00_f);
    const u64 C_1MBDT = pk2(1.0f - BETA * DT);
    const u64 ONE     = pk2(1.0f);

    // load 2 adjacent trajectories packed
    const u64* xr = (const u64*)x_in;
    int rb = B2;
    u64 X = xr[i];
    u64 Y = xr[rb + i];
    u64 Z = xr[2 * rb + i];

    u64 P1 = ONE, P2 = ONE;   // running products of row-1/row-2 norm^2

    #pragma unroll 1
    for (int s = 0; s < TSTEPS; ++s) {
        // ---------- RK4 (faithful: k4 at x + dt*k2) ----------
        u64 k1x = f2mul(C_SIG, f2sub(Y, X, NEG1));
        u64 k1y = f2fma(X, f2fma(Z, NEG1, C_RHO), f2neg(Y));
        u64 k1z = f2fma(X, Y, f2mul(C_NBETA, Z));

        u64 ax = f2fma(C_HDT, k1x, X);
        u64 ay = f2fma(C_HDT, k1y, Y);
        u64 az = f2fma(C_HDT, k1z, Z);
        u64 k2x = f2mul(C_SIG, f2sub(ay, ax, NEG1));
        u64 k2y = f2fma(ax, f2fma(az, NEG1, C_RHO), f2neg(ay));
        u64 k2z = f2fma(ax, ay, f2mul(C_NBETA, az));

        ax = f2fma(C_HDT, k2x, X);
        ay = f2fma(C_HDT, k2y, Y);
        az = f2fma(C_HDT, k2z, Z);
        u64 k3x = f2mul(C_SIG, f2sub(ay, ax, NEG1));
        u64 k3y = f2fma(ax, f2fma(az, NEG1, C_RHO), f2neg(ay));
        u64 k3z = f2fma(ax, ay, f2mul(C_NBETA, az));

        ax = f2fma(C_DT, k2x, X);
        ay = f2fma(C_DT, k2y, Y);
        az = f2fma(C_DT, k2z, Z);
        u64 k4x = f2mul(C_SIG, f2sub(ay, ax, NEG1));
        u64 k4y = f2fma(ax, f2fma(az, NEG1, C_RHO), f2neg(ay));
        u64 k4z = f2fma(ax, ay, f2mul(C_NBETA, az));

        X = f2fma(C_DT6, f2fma(C_TWO, f2add(k2x, k3x), f2add(k1x, k4x)), X);
        Y = f2fma(C_DT6, f2fma(C_TWO, f2add(k2y, k3y), f2add(k1y, k4y)), Y);
        Z = f2fma(C_DT6, f2fma(C_TWO, f2add(k2z, k3z), f2add(k1z, k4z)), Z);

        // ---------- MGS on rows of P = I + dt*J(x), Gram-only (Q eliminated) ----------
        // P rows: r0 = (a, s, 0) const;  r1 = (w10, 1-dt, -xdt);  r2 = (ydt, xdt, 1-bdt)
        u64 w10  = f2fma(Z, C_NDT, C_RHODT);      // dt*(rho - z)
        u64 xdt  = f2mul(X, C_DT);
        u64 nxdt = f2neg(xdt);
        u64 ydt  = f2mul(Y, C_DT);

        // project r1 against r0:  c10 = (r0.r1)/d00
        u64 d01 = f2fma(w10, C_A, C_S99);         // a*w10 + s*(1-dt)
        u64 c10 = f2mul(d01, C_I00);
        u64 r1x = f2fma(c10, C_NA, w10);
        u64 r1y = f2fma(c10, C_NS, C_99);
        // r1z = -xdt (unchanged)

        // project r2 against r0:  c20 = (r0.r2)/d00
        u64 d02 = f2fma(ydt, C_A, f2mul(xdt, C_S));
        u64 c20 = f2mul(d02, C_I00);
        u64 r2x = f2fma(c20, C_NA, ydt);
        u64 r2y = f2fma(c20, C_NS, xdt);
        // r2z = 1 - beta*dt (const)

        // d11 = |r1'|^2
        u64 d11 = f2fma(r1x, r1x, f2fma(r1y, r1y, f2mul(xdt, xdt)));
        u64 i11 = f2rcp(d11);

        // project r2 against r1':  c21 = (r1'.r2')/d11
        u64 d12 = f2fma(r1x, r2x, f2fma(r1y, r2y, f2mul(nxdt, C_1MBDT)));
        u64 nc21 = f2neg(f2mul(d12, i11));
        u64 f2x = f2fma(nc21, r1x, r2x);
        u64 f2y = f2fma(nc21, r1y, r2y);
        u64 f2z = f2fma(nc21, nxdt, C_1MBDT);

        u64 d22 = f2fma(f2x, f2x, f2fma(f2y, f2y, f2mul(f2z, f2z)));

        P1 = f2mul(P1, d11);
        P2 = f2mul(P2, d22);
    }

    // lya_k = 0.5 * log(prod n_k^2) / (t_last + dt);  lya_0 is a pure constant
    float tl = tseq[T - 1];
    float sc = __fdividef(0.5f, tl + DT);
    float ly0 = sc * (float)TSTEPS * __logf(d00_f);

    float2* o2 = (float2*)out;
    o2[i] = make_float2(ly0, ly0);
    {
        float lo = sc * __logf(__uint_as_float((unsigned)P1));
        float hi = sc * __logf(__uint_as_float((unsigned)(P1 >> 32)));
        o2[rb + i] = make_float2(lo, hi);
        lo = sc * __logf(__uint_as_float((unsigned)P2));
        hi = sc * __logf(__uint_as_float((unsigned)(P2 >> 32)));
        o2[2 * rb + i] = make_float2(lo, hi);
    }
    if (write_xf) {
        u64* o8 = (u64*)out;
        o8[3 * rb + i] = X;
        o8[4 * rb + i] = Y;
        o8[5 * rb + i] = Z;
    }
}

extern "C" void kernel_launch(void* const* d_in, const int* in_sizes, int n_in,
                              void* d_out, int out_size) {
    const float* x    = (const float*)d_in[0];
    const float* tseq = (const float*)d_in[1];
    float* out = (float*)d_out;

    int B = in_sizes[0] / 3;          // x is [3, B]
    int T = in_sizes[1];
    int write_xf = (out_size >= 6 * B) ? 1 : 0;

    int B2 = B >> 1;                  // 2 trajectories per thread
    int threads = 128;
    int blocks = (B2 + threads - 1) / threads;
    lya_spec_kernel<<<blocks, threads>>>(x, tseq, out, B, T, write_xf);
}

// round 4
// speedup vs baseline: 1.9884x; 1.1050x over previous
#include <cuda_runtime.h>

#define SIGMA 10.0f
#define RHO   28.0f
#define BETA  (8.0f / 3.0f)
#define DT    0.01f
#define TSTEPS 64

using u64 = unsigned long long;

// ---- packed f32x2 primitives (Blackwell FFMA2 path) ----
__device__ __forceinline__ u64 f2fma(u64 a, u64 b, u64 c) {
    u64 d; asm("fma.rn.f32x2 %0, %1, %2, %3;" : "=l"(d) : "l"(a), "l"(b), "l"(c)); return d;
}
__device__ __forceinline__ u64 f2add(u64 a, u64 b) {
    u64 d; asm("add.rn.f32x2 %0, %1, %2;" : "=l"(d) : "l"(a), "l"(b)); return d;
}
__device__ __forceinline__ u64 f2mul(u64 a, u64 b) {
    u64 d; asm("mul.rn.f32x2 %0, %1, %2;" : "=l"(d) : "l"(a), "l"(b)); return d;
}
__device__ __forceinline__ u64 pk2(float f) {
    unsigned u = __float_as_uint(f);
    return (u64)u * 0x0000000100000001ULL;
}
// a - b via fma(b, -1, a): stays on fma pipe, no ALU
__device__ __forceinline__ u64 f2sub(u64 a, u64 b, u64 NEG1) { return f2fma(b, NEG1, a); }

// packed reciprocal via 2x MUFU rcp.approx (register-pair halves, no real shifts)
__device__ __forceinline__ u64 f2rcp(u64 a) {
    float lo = __uint_as_float((unsigned)a);
    float hi = __uint_as_float((unsigned)(a >> 32));
    float rl, rh;
    asm("rcp.approx.f32 %0, %1;" : "=f"(rl) : "f"(lo));
    asm("rcp.approx.f32 %0, %1;" : "=f"(rh) : "f"(hi));
    return (u64)__float_as_uint(rl) | ((u64)__float_as_uint(rh) << 32);
}

__global__ void __launch_bounds__(64)
lya_spec_kernel(const float* __restrict__ x_in,
                const float* __restrict__ tseq,
                float* __restrict__ out,
                int B, int T, int write_xf)
{
    int i = blockIdx.x * blockDim.x + threadIdx.x;   // pair index
    int B2 = B >> 1;
    if (i >= B2) return;

    // ---- constants ----
    const float a_f    = 1.0f - DT * SIGMA;          // 0.9
    const float s_f    = DT * SIGMA;                 // 0.1
    const float d00_f  = a_f * a_f + s_f * s_f;      // 0.82
    const float q_f    = 1.0f - DT;                  // 0.99
    const float bdt_f  = 1.0f - BETA * DT;           // 1 - 8/300

    const u64 NEG1    = pk2(-1.0f);
    const u64 C_SIG   = pk2(SIGMA);
    const u64 C_NRHO  = pk2(-RHO);
    const u64 C_NBETA = pk2(-BETA);
    const u64 C_HDT   = pk2(0.5f * DT);
    const u64 C_NHDT  = pk2(-0.5f * DT);
    const u64 C_DT    = pk2(DT);
    const u64 C_NDT   = pk2(-DT);
    const u64 C_TWO   = pk2(2.0f);
    const u64 C_DT6   = pk2(DT / 6.0f);
    const u64 C_NDT6  = pk2(-DT / 6.0f);
    const u64 C_RHODT = pk2(RHO * DT);
    const u64 C_A     = pk2(a_f);
    const u64 C_S     = pk2(s_f);
    const u64 C_S99   = pk2(s_f * q_f);              // s*(1-dt)
    const u64 C_NI00  = pk2(-1.0f / d00_f);
    const u64 C_99SQ  = pk2(q_f * q_f);
    const u64 C_BDT2  = pk2(bdt_f * bdt_f);
    const u64 C_K     = pk2((BETA - 1.0f) * DT);     // (1-dt) - (1-beta*dt) folded
    const u64 ONE     = pk2(1.0f);

    // load 2 adjacent trajectories packed
    const u64* xr = (const u64*)x_in;
    int rb = B2;
    u64 X = xr[i];
    u64 Y = xr[rb + i];
    u64 Z = xr[2 * rb + i];

    u64 P1 = ONE, P2 = ONE;   // running products of row-1/row-2 norm^2

    #pragma unroll 1
    for (int s = 0; s < TSTEPS; ++s) {
        // ---------- RK4, carrying NEGATED y-derivatives (no sign flips) ----------
        // k1 at (X,Y,Z)
        u64 k1x  = f2mul(C_SIG, f2sub(Y, X, NEG1));
        u64 nw   = f2add(Z, C_NRHO);                 // z - rho
        u64 nk1y = f2fma(X, nw, Y);                  // -(x(rho-z) - y)
        u64 k1z  = f2fma(X, Y, f2mul(C_NBETA, Z));

        // k2 at x + h*k1
        u64 ax = f2fma(C_HDT,  k1x,  X);
        u64 ay = f2fma(C_NHDT, nk1y, Y);
        u64 az = f2fma(C_HDT,  k1z,  Z);
        u64 k2x  = f2mul(C_SIG, f2sub(ay, ax, NEG1));
        nw       = f2add(az, C_NRHO);
        u64 nk2y = f2fma(ax, nw, ay);
        u64 k2z  = f2fma(ax, ay, f2mul(C_NBETA, az));

        // k3 at x + h*k2
        ax = f2fma(C_HDT,  k2x,  X);
        ay = f2fma(C_NHDT, nk2y, Y);
        az = f2fma(C_HDT,  k2z,  Z);
        u64 k3x  = f2mul(C_SIG, f2sub(ay, ax, NEG1));
        nw       = f2add(az, C_NRHO);
        u64 nk3y = f2fma(ax, nw, ay);
        u64 k3z  = f2fma(ax, ay, f2mul(C_NBETA, az));

        // k4 at x + dt*k2 (faithful to reference bug)
        ax = f2fma(C_DT,  k2x,  X);
        ay = f2fma(C_NDT, nk2y, Y);
        az = f2fma(C_DT,  k2z,  Z);
        u64 k4x  = f2mul(C_SIG, f2sub(ay, ax, NEG1));
        nw       = f2add(az, C_NRHO);
        u64 nk4y = f2fma(ax, nw, ay);
        u64 k4z  = f2fma(ax, ay, f2mul(C_NBETA, az));

        X = f2fma(C_DT6,  f2fma(C_TWO, f2add(k2x,  k3x),  f2add(k1x,  k4x)),  X);
        Y = f2fma(C_NDT6, f2fma(C_TWO, f2add(nk2y, nk3y), f2add(nk1y, nk4y)), Y);
        Z = f2fma(C_DT6,  f2fma(C_TWO, f2add(k2z,  k3z),  f2add(k1z,  k4z)),  Z);

        // ---------- Gram-only MGS on rows of P = I + dt*J(x) ----------
        // r0 = (a, s, 0) const; r1 = (w10, 1-dt, -xdt); r2 = (ydt, xdt, 1-bdt)
        u64 w10 = f2fma(Z, C_NDT, C_RHODT);          // dt*(rho - z)
        u64 xdt = f2mul(X, C_DT);
        u64 ydt = f2mul(Y, C_DT);
        u64 xx2 = f2mul(xdt, xdt);

        u64 d01 = f2fma(w10, C_A, C_S99);                        // r0.r1
        u64 d02 = f2fma(ydt, C_A, f2mul(xdt, C_S));              // r0.r2
        u64 d12 = f2fma(w10, ydt, f2mul(xdt, C_K));              // r1.r2 (const-folded)
        u64 r1s = f2fma(w10, w10, f2add(xx2, C_99SQ));           // |r1|^2
        u64 r2s = f2fma(ydt, ydt, f2add(xx2, C_BDT2));           // |r2|^2

        u64 m01 = f2mul(d01, C_NI00);                            // -d01/d00
        u64 m02 = f2mul(d02, C_NI00);                            // -d02/d00

        u64 d11  = f2fma(m01, d01, r1s);                         // |r1'|^2
        u64 d2p  = f2fma(m02, d02, r2s);                         // |r2 - c20 r0|^2
        u64 d12p = f2fma(m02, d01, d12);                         // r1'.r2'

        u64 i11 = f2rcp(d11);
        u64 t   = f2mul(d12p, d12p);
        u64 u   = f2mul(t, i11);
        u64 d22 = f2fma(u, NEG1, d2p);                           // |r2''|^2

        P1 = f2mul(P1, d11);
        P2 = f2mul(P2, d22);
    }

    // lya_k = 0.5 * log(prod n_k^2) / (t_last + dt);  lya_0 is a pure constant
    float tl = tseq[T - 1];
    float sc = __fdividef(0.5f, tl + DT);
    float ly0 = sc * (float)TSTEPS * __logf(d00_f);

    float2* o2 = (float2*)out;
    o2[i] = make_float2(ly0, ly0);
    {
        float lo = sc * __logf(__uint_as_float((unsigned)P1));
        float hi = sc * __logf(__uint_as_float((unsigned)(P1 >> 32)));
        o2[rb + i] = make_float2(lo, hi);
        lo = sc * __logf(__uint_as_float((unsigned)P2));
        hi = sc * __logf(__uint_as_float((unsigned)(P2 >> 32)));
        o2[2 * rb + i] = make_float2(lo, hi);
    }
    if (write_xf) {
        u64* o8 = (u64*)out;
        o8[3 * rb + i] = X;
        o8[4 * rb + i] = Y;
        o8[5 * rb + i] = Z;
    }
}

extern "C" void kernel_launch(void* const* d_in, const int* in_sizes, int n_in,
                              void* d_out, int out_size) {
    const float* x    = (const float*)d_in[0];
    const float* tseq = (const float*)d_in[1];
    float* out = (float*)d_out;

    int B = in_sizes[0] / 3;          // x is [3, B]
    int T = in_sizes[1];
    int write_xf = (out_size >= 6 * B) ? 1 : 0;

    int B2 = B >> 1;                  // 2 trajectories per thread
    int threads = 64;                 // small blocks -> better wave balance
    int blocks = (B2 + threads - 1) / threads;
    lya_spec_kernel<<<blocks, threads>>>(x, tseq, out, B, T, write_xf);
}

// round 5
// speedup vs baseline: 2.0783x; 1.0452x over previous
#include <cuda_runtime.h>

#define SIGMA 10.0f
#define RHO   28.0f
#define BETA  (8.0f / 3.0f)
#define DT    0.01f
#define TSTEPS 64

using u64 = unsigned long long;

// ---- packed f32x2 primitives (Blackwell FFMA2 path) ----
__device__ __forceinline__ u64 f2fma(u64 a, u64 b, u64 c) {
    u64 d; asm("fma.rn.f32x2 %0, %1, %2, %3;" : "=l"(d) : "l"(a), "l"(b), "l"(c)); return d;
}
__device__ __forceinline__ u64 f2add(u64 a, u64 b) {
    u64 d; asm("add.rn.f32x2 %0, %1, %2;" : "=l"(d) : "l"(a), "l"(b)); return d;
}
__device__ __forceinline__ u64 f2mul(u64 a, u64 b) {
    u64 d; asm("mul.rn.f32x2 %0, %1, %2;" : "=l"(d) : "l"(a), "l"(b)); return d;
}
__device__ __forceinline__ u64 pk2(float f) {
    unsigned u = __float_as_uint(f);
    return (u64)u * 0x0000000100000001ULL;
}
// a - b via fma(b, -1, a): stays on fma pipe, no ALU
__device__ __forceinline__ u64 f2sub(u64 a, u64 b, u64 NEG1) { return f2fma(b, NEG1, a); }

// packed reciprocal via 2x MUFU rcp.approx
__device__ __forceinline__ u64 f2rcp(u64 a) {
    float lo = __uint_as_float((unsigned)a);
    float hi = __uint_as_float((unsigned)(a >> 32));
    float rl, rh;
    asm("rcp.approx.f32 %0, %1;" : "=f"(rl) : "f"(lo));
    asm("rcp.approx.f32 %0, %1;" : "=f"(rh) : "f"(hi));
    return (u64)__float_as_uint(rl) | ((u64)__float_as_uint(rh) << 32);
}

__global__ void __launch_bounds__(64)
lya_spec_kernel(const float* __restrict__ x_in,
                const float* __restrict__ tseq,
                float* __restrict__ out,
                int B, int T, int write_xf)
{
    int i = blockIdx.x * blockDim.x + threadIdx.x;   // pair index
    int B2 = B >> 1;
    if (i >= B2) return;

    // ---- constants ----
    const float a_f    = 1.0f - DT * SIGMA;          // 0.9
    const float s_f    = DT * SIGMA;                 // 0.1
    const float d00_f  = a_f * a_f + s_f * s_f;      // 0.82
    const float q_f    = 1.0f - DT;                  // 0.99
    const float bdt_f  = 1.0f - BETA * DT;

    const u64 NEG1    = pk2(-1.0f);
    const u64 C_SIG   = pk2(SIGMA);
    const u64 C_NRHO  = pk2(-RHO);
    const u64 C_NBETA = pk2(-BETA);
    const u64 C_HDT   = pk2(0.5f * DT);
    const u64 C_NHDT  = pk2(-0.5f * DT);
    const u64 C_DT    = pk2(DT);
    const u64 C_NDT   = pk2(-DT);
    const u64 C_TWO   = pk2(2.0f);
    const u64 C_DT6   = pk2(DT / 6.0f);
    const u64 C_NDT6  = pk2(-DT / 6.0f);
    const u64 C_RHODT = pk2(RHO * DT);
    const u64 C_A     = pk2(a_f);
    const u64 C_S     = pk2(s_f);
    const u64 C_S99   = pk2(s_f * q_f);
    const u64 C_NI00  = pk2(-1.0f / d00_f);
    const u64 C_99SQ  = pk2(q_f * q_f);
    const u64 C_BDT2  = pk2(bdt_f * bdt_f);
    const u64 C_K     = pk2((BETA - 1.0f) * DT);
    const u64 ONE     = pk2(1.0f);

    // load 2 adjacent trajectories packed
    const u64* xr = (const u64*)x_in;
    int rb = B2;
    u64 X = xr[i];
    u64 Y = xr[rb + i];
    u64 Z = xr[2 * rb + i];

    u64 P1 = ONE, P2 = ONE;   // running products of row-1/row-2 norm^2

    // unroll 2: lets ptxas overlap iteration i's Gram tail with
    // iteration i+1's RK4 head (cross-iteration ILP in the in-order schedule)
    #pragma unroll 2
    for (int s = 0; s < TSTEPS; ++s) {
        // ---------- RK4, carrying NEGATED y-derivatives (no sign flips) ----------
        u64 k1x  = f2mul(C_SIG, f2sub(Y, X, NEG1));
        u64 nw   = f2add(Z, C_NRHO);                 // z - rho
        u64 nk1y = f2fma(X, nw, Y);
        u64 k1z  = f2fma(X, Y, f2mul(C_NBETA, Z));

        u64 ax = f2fma(C_HDT,  k1x,  X);
        u64 ay = f2fma(C_NHDT, nk1y, Y);
        u64 az = f2fma(C_HDT,  k1z,  Z);
        u64 k2x  = f2mul(C_SIG, f2sub(ay, ax, NEG1));
        nw       = f2add(az, C_NRHO);
        u64 nk2y = f2fma(ax, nw, ay);
        u64 k2z  = f2fma(ax, ay, f2mul(C_NBETA, az));

        ax = f2fma(C_HDT,  k2x,  X);
        ay = f2fma(C_NHDT, nk2y, Y);
        az = f2fma(C_HDT,  k2z,  Z);
        u64 k3x  = f2mul(C_SIG, f2sub(ay, ax, NEG1));
        nw       = f2add(az, C_NRHO);
        u64 nk3y = f2fma(ax, nw, ay);
        u64 k3z  = f2fma(ax, ay, f2mul(C_NBETA, az));

        ax = f2fma(C_DT,  k2x,  X);
        ay = f2fma(C_NDT, nk2y, Y);
        az = f2fma(C_DT,  k2z,  Z);
        u64 k4x  = f2mul(C_SIG, f2sub(ay, ax, NEG1));
        nw       = f2add(az, C_NRHO);
        u64 nk4y = f2fma(ax, nw, ay);
        u64 k4z  = f2fma(ax, ay, f2mul(C_NBETA, az));

        X = f2fma(C_DT6,  f2fma(C_TWO, f2add(k2x,  k3x),  f2add(k1x,  k4x)),  X);
        Y = f2fma(C_NDT6, f2fma(C_TWO, f2add(nk2y, nk3y), f2add(nk1y, nk4y)), Y);
        Z = f2fma(C_DT6,  f2fma(C_TWO, f2add(k2z,  k3z),  f2add(k1z,  k4z)),  Z);

        // ---------- Gram-only MGS on rows of P = I + dt*J(x) ----------
        u64 w10 = f2fma(Z, C_NDT, C_RHODT);          // dt*(rho - z)
        u64 xdt = f2mul(X, C_DT);
        u64 ydt = f2mul(Y, C_DT);
        u64 xx2 = f2mul(xdt, xdt);

        u64 d01 = f2fma(w10, C_A, C_S99);                        // r0.r1
        u64 d02 = f2fma(ydt, C_A, f2mul(xdt, C_S));              // r0.r2
        u64 d12 = f2fma(w10, ydt, f2mul(xdt, C_K));              // r1.r2
        u64 r1s = f2fma(w10, w10, f2add(xx2, C_99SQ));           // |r1|^2
        u64 r2s = f2fma(ydt, ydt, f2add(xx2, C_BDT2));           // |r2|^2

        u64 m01 = f2mul(d01, C_NI00);
        u64 m02 = f2mul(d02, C_NI00);

        u64 d11  = f2fma(m01, d01, r1s);
        u64 d2p  = f2fma(m02, d02, r2s);
        u64 d12p = f2fma(m02, d01, d12);

        u64 i11 = f2rcp(d11);
        u64 t   = f2mul(d12p, d12p);
        u64 u   = f2mul(t, i11);
        u64 d22 = f2fma(u, NEG1, d2p);

        P1 = f2mul(P1, d11);
        P2 = f2mul(P2, d22);
    }

    // lya_k = 0.5 * log(prod n_k^2) / (t_last + dt);  lya_0 is a pure constant
    float tl = tseq[T - 1];
    float sc = __fdividef(0.5f, tl + DT);
    float ly0 = sc * (float)TSTEPS * __logf(d00_f);

    float2* o2 = (float2*)out;
    o2[i] = make_float2(ly0, ly0);
    {
        float lo = sc * __logf(__uint_as_float((unsigned)P1));
        float hi = sc * __logf(__uint_as_float((unsigned)(P1 >> 32)));
        o2[rb + i] = make_float2(lo, hi);
        lo = sc * __logf(__uint_as_float((unsigned)P2));
        hi = sc * __logf(__uint_as_float((unsigned)(P2 >> 32)));
        o2[2 * rb + i] = make_float2(lo, hi);
    }
    if (write_xf) {
        u64* o8 = (u64*)out;
        o8[3 * rb + i] = X;
        o8[4 * rb + i] = Y;
        o8[5 * rb + i] = Z;
    }
}

extern "C" void kernel_launch(void* const* d_in, const int* in_sizes, int n_in,
                              void* d_out, int out_size) {
    const float* x    = (const float*)d_in[0];
    const float* tseq = (const float*)d_in[1];
    float* out = (float*)d_out;

    int B = in_sizes[0] / 3;          // x is [3, B]
    int T = in_sizes[1];
    int write_xf = (out_size >= 6 * B) ? 1 : 0;

    int B2 = B >> 1;                  // 2 trajectories per thread
    int threads = 64;
    int blocks = (B2 + threads - 1) / threads;
    lya_spec_kernel<<<blocks, threads>>>(x, tseq, out, B, T, write_xf);
}